// round 4
// baseline (speedup 1.0000x reference)
#include <cuda_runtime.h>

#define Bn 32
#define Sn 2048
#define Dn 1024

// ---- scratch (no allocations allowed) ----
__device__ float g_ysp[2 * Bn * Dn];   // per-half-S column sums of E
__device__ float g_u[Bn * Dn];         // u[b,d] = sum_e W[d,e] * ys_sum[b,e]  (unscaled)
__device__ float g_acc[256 * Dn];      // per-(b,chunk) partial zs accumulators
__device__ float g_m[256];             // per-(b,chunk) softmax max
__device__ float g_Z[256];             // per-(b,chunk) softmax denom (scaled to g_m)

// ===================== K1: column sums of E over S (split in 2) =====================
// grid 256 = (b:32) x (dtile:4) x (shalf:2), 256 threads; also zeroes g_u.
__global__ __launch_bounds__(256) void k1_colsum(const float* __restrict__ E) {
    int bx = blockIdx.x;
    int b  = bx >> 3;
    int dt = (bx >> 1) & 3;
    int sh = bx & 1;
    int d  = dt * 256 + threadIdx.x;
    const float* p = E + ((size_t)(b * Sn + sh * 1024)) * Dn + d;
    float s0 = 0.f, s1 = 0.f, s2 = 0.f, s3 = 0.f;
    #pragma unroll 4
    for (int s = 0; s < 1024; s += 4) {
        s0 += p[(size_t)(s + 0) * Dn];
        s1 += p[(size_t)(s + 1) * Dn];
        s2 += p[(size_t)(s + 2) * Dn];
        s3 += p[(size_t)(s + 3) * Dn];
    }
    g_ysp[sh * Bn * Dn + b * Dn + d] = (s0 + s1) + (s2 + s3);
    if (threadIdx.x < 128) g_u[bx * 128 + threadIdx.x] = 0.f;
}

// ===================== K2: u[b,d] = sum_e W[d,e] * ys_sum[b,e] =====================
// grid 256 = (dtile:16 of 64 d) x (esplit:16 of 64 e), atomicAdd partials.
__global__ __launch_bounds__(256) void k2_u(const float* __restrict__ W) {
    __shared__ float Ws[64 * 65];   // padded rows: bank-conflict-free column reads
    __shared__ float Ys[32 * 64];
    int dt = blockIdx.x >> 4, es = blockIdx.x & 15;
    int d0 = dt * 64, e0 = es * 64;
    int t = threadIdx.x;
    #pragma unroll
    for (int k = 0; k < 16; k++) {
        int idx = t + k * 256;
        int r = idx >> 6, c = idx & 63;
        Ws[r * 65 + c] = W[(size_t)(d0 + r) * Dn + e0 + c];
    }
    #pragma unroll
    for (int k = 0; k < 8; k++) {
        int idx = t + k * 256;
        int b = idx >> 6, c = idx & 63;
        Ys[b * 64 + c] = g_ysp[b * Dn + e0 + c] + g_ysp[Bn * Dn + b * Dn + e0 + c];
    }
    __syncthreads();
    int bg = t >> 5, dg = t & 31;   // warp owns 4 consecutive b; lane = d within tile
    float a00 = 0, a01 = 0, a10 = 0, a11 = 0, a20 = 0, a21 = 0, a30 = 0, a31 = 0;
    #pragma unroll 8
    for (int c = 0; c < 64; c++) {
        float w0 = Ws[dg * 65 + c];
        float w1 = Ws[(dg + 32) * 65 + c];
        float y0 = Ys[(bg * 4 + 0) * 64 + c];
        float y1 = Ys[(bg * 4 + 1) * 64 + c];
        float y2 = Ys[(bg * 4 + 2) * 64 + c];
        float y3 = Ys[(bg * 4 + 3) * 64 + c];
        a00 += y0 * w0; a01 += y0 * w1;
        a10 += y1 * w0; a11 += y1 * w1;
        a20 += y2 * w0; a21 += y2 * w1;
        a30 += y3 * w0; a31 += y3 * w1;
    }
    atomicAdd(&g_u[(bg * 4 + 0) * Dn + d0 + dg],      a00);
    atomicAdd(&g_u[(bg * 4 + 0) * Dn + d0 + dg + 32], a01);
    atomicAdd(&g_u[(bg * 4 + 1) * Dn + d0 + dg],      a10);
    atomicAdd(&g_u[(bg * 4 + 1) * Dn + d0 + dg + 32], a11);
    atomicAdd(&g_u[(bg * 4 + 2) * Dn + d0 + dg],      a20);
    atomicAdd(&g_u[(bg * 4 + 2) * Dn + d0 + dg + 32], a21);
    atomicAdd(&g_u[(bg * 4 + 3) * Dn + d0 + dg],      a30);
    atomicAdd(&g_u[(bg * 4 + 3) * Dn + d0 + dg + 32], a31);
}

// ===================== K3: fused f + online softmax + partial zs =====================
// grid 256 = (b:32) x (chunk:8 of 256 rows); 8 warps/block, warp owns 32 rows.
// Each E row is read ONCE: used for the dot and immediately for the weighted acc.
__global__ __launch_bounds__(256, 2) void k3_main(
    const float* __restrict__ E, const void* __restrict__ maskp,
    float* __restrict__ fout)
{
    __shared__ float sAcc[8][1024];
    __shared__ float sM[8], sZ[8];
    __shared__ int sMode;

    int t = threadIdx.x, w = t >> 5, lane = t & 31;
    int bx = blockIdx.x;
    int b = bx >> 3, chunk = bx & 7;

    // mask dtype probe: 0=uint8, 1=int32, 2=float32
    if (t == 0) {
        const unsigned int* mu = (const unsigned int*)maskp;
        bool allLe1 = true, allF = true;
        for (int i = 0; i < 64; i++) {
            unsigned int v = mu[i];
            if (v > 1u) allLe1 = false;
            if (v != 0u && v != 0x3F800000u) allF = false;
        }
        sMode = allLe1 ? 1 : (allF ? 2 : 0);
    }
    __syncthreads();
    int mode = sMode;

    // lane-resident u slice (cols j*128 + lane*4 .. +3), scaled by 1/S (mean fold)
    const float4* u4 = reinterpret_cast<const float4*>(g_u + b * Dn);
    float4 u[8];
    const float invS = 1.0f / 2048.0f;
    #pragma unroll
    for (int j = 0; j < 8; j++) {
        float4 v = u4[j * 32 + lane];
        u[j] = make_float4(v.x * invS, v.y * invS, v.z * invS, v.w * invS);
    }

    float4 acc[8];
    #pragma unroll
    for (int j = 0; j < 8; j++) acc[j] = make_float4(0.f, 0.f, 0.f, 0.f);
    float m = -1.0e30f, Z = 0.f;

    int sBase = chunk * 256 + w * 32;
    const float4* E4 = reinterpret_cast<const float4*>(E);

    for (int i = 0; i < 32; i++) {
        int s = sBase + i;
        const float4* row = E4 + (size_t)(b * Sn + s) * 256;
        float4 r[8];
        float dot = 0.f;
        #pragma unroll
        for (int j = 0; j < 8; j++) {
            r[j] = row[j * 32 + lane];
            dot += r[j].x * u[j].x + r[j].y * u[j].y + r[j].z * u[j].z + r[j].w * u[j].w;
        }
        #pragma unroll
        for (int o = 16; o; o >>= 1) dot += __shfl_xor_sync(0xffffffffu, dot, o);

        int midx = b * Sn + s;
        bool mk;
        if (mode == 1)      mk = ((const int*)maskp)[midx] != 0;
        else if (mode == 2) mk = ((const float*)maskp)[midx] != 0.f;
        else                mk = ((const unsigned char*)maskp)[midx] != 0;
        float f = mk ? dot : -1.0e9f;
        if (lane == 0) fout[midx] = f;   // raw logit; K4 normalizes

        if (f > m) {                      // rare rescale (~ln(32) times)
            float sc = __expf(m - f);
            #pragma unroll
            for (int j = 0; j < 8; j++) {
                acc[j].x *= sc; acc[j].y *= sc; acc[j].z *= sc; acc[j].w *= sc;
            }
            Z *= sc;
            m = f;
        }
        float p = __expf(f - m);
        Z += p;
        #pragma unroll
        for (int j = 0; j < 8; j++) {
            acc[j].x += p * r[j].x; acc[j].y += p * r[j].y;
            acc[j].z += p * r[j].z; acc[j].w += p * r[j].w;
        }
    }

    // per-warp results -> shared, combine across the 8 warps in block
    float4* sA = reinterpret_cast<float4*>(&sAcc[w][0]);
    #pragma unroll
    for (int j = 0; j < 8; j++) sA[j * 32 + lane] = acc[j];
    if (lane == 0) { sM[w] = m; sZ[w] = Z; }
    __syncthreads();

    float M = sM[0];
    #pragma unroll
    for (int k = 1; k < 8; k++) M = fmaxf(M, sM[k]);
    float sc[8];
    #pragma unroll
    for (int k = 0; k < 8; k++) sc[k] = __expf(sM[k] - M);
    if (t == 0) {
        float Zb = 0.f;
        #pragma unroll
        for (int k = 0; k < 8; k++) Zb += sZ[k] * sc[k];
        g_Z[bx] = Zb;
        g_m[bx] = M;
    }
    float4 v = make_float4(0.f, 0.f, 0.f, 0.f);
    #pragma unroll
    for (int k = 0; k < 8; k++) {
        float4 a = reinterpret_cast<const float4*>(&sAcc[k][0])[t];
        v.x += sc[k] * a.x; v.y += sc[k] * a.y;
        v.z += sc[k] * a.z; v.w += sc[k] * a.w;
    }
    reinterpret_cast<float4*>(g_acc)[bx * 256 + t] = v;
}

// ===================== K4: merge chunks, write zs, normalize f =====================
__global__ __launch_bounds__(256) void k4_final(float* __restrict__ out) {
    int b = blockIdx.x, t = threadIdx.x;
    float M = g_m[b * 8];
    #pragma unroll
    for (int c = 1; c < 8; c++) M = fmaxf(M, g_m[b * 8 + c]);
    float sc[8];
    float Z = 0.f;
    #pragma unroll
    for (int c = 0; c < 8; c++) {
        sc[c] = __expf(g_m[b * 8 + c] - M);
        Z += g_Z[b * 8 + c] * sc[c];
    }
    float rinv = 1.0f / Z;

    float4 v = make_float4(0.f, 0.f, 0.f, 0.f);
    #pragma unroll
    for (int c = 0; c < 8; c++) {
        float4 a = reinterpret_cast<const float4*>(g_acc)[(b * 8 + c) * 256 + t];
        v.x += sc[c] * a.x; v.y += sc[c] * a.y;
        v.z += sc[c] * a.z; v.w += sc[c] * a.w;
    }
    v.x *= rinv; v.y *= rinv; v.z *= rinv; v.w *= rinv;
    reinterpret_cast<float4*>(out)[b * 256 + t] = v;   // zs[b, 4t..4t+3]

    float* fptr = out + Bn * Dn;
    #pragma unroll
    for (int k = 0; k < 8; k++) {
        int idx = b * Sn + t + k * 256;
        fptr[idx] = __expf(fptr[idx] - M) * rinv;
    }
}

extern "C" void kernel_launch(void* const* d_in, const int* in_sizes, int n_in,
                              void* d_out, int out_size) {
    const float* E    = (const float*)d_in[0];
    const void*  mask = d_in[1];
    const float* W    = (const float*)d_in[2];
    float* out = (float*)d_out;

    k1_colsum<<<256, 256>>>(E);
    k2_u     <<<256, 256>>>(W);
    k3_main  <<<256, 256>>>(E, mask, out + Bn * Dn);
    k4_final <<<32, 256>>>(out);
}